// round 13
// baseline (speedup 1.0000x reference)
#include <cuda_runtime.h>
#include <cuda_fp16.h>
#include <math.h>
#include <stdint.h>

#define BATCH 2
#define SEQ 4096
#define DIM 512
#define NH 8
#define HD 64
#define MROWS (BATCH * SEQ)   // 8192
#define NSPLIT 4
#define KITER_PER_SPLIT (SEQ / 64 / NSPLIT)   // 16

// Scratch (allocation-free rule: __device__ globals)
__device__ __align__(16) __half g_Xh[MROWS * DIM];
__device__ __align__(16) __half g_Wh[3 * DIM * DIM];
__device__ __align__(16) __half g_Woh[DIM * DIM];
__device__ __align__(16) __half g_Qh[MROWS * DIM];
__device__ __align__(16) __half g_Kh[MROWS * DIM];
__device__ __align__(16) __half g_Vh[MROWS * DIM];
__device__ __align__(16) __half g_Oh[MROWS * DIM];
__device__ __align__(16) __half g_Opf[NSPLIT][MROWS * DIM];       // 32 MB fp16 partials
__device__ __align__(16) float  g_lp[NSPLIT][BATCH * NH * SEQ];   // 1 MB

// ---------------------------------------------------------------------------
// PTX helpers (sm_80-compatible: mma.sync / ldmatrix / cp.async)
// ---------------------------------------------------------------------------
__device__ __forceinline__ uint32_t smem_u32(const void* p) {
    uint32_t a;
    asm("{ .reg .u64 t; cvta.to.shared.u64 t, %1; cvt.u32.u64 %0, t; }"
        : "=r"(a) : "l"(p));
    return a;
}
__device__ __forceinline__ void mma16816(float* c, const uint32_t* a,
                                         uint32_t b0, uint32_t b1) {
    asm volatile(
        "mma.sync.aligned.m16n8k16.row.col.f32.f16.f16.f32 "
        "{%0,%1,%2,%3}, {%4,%5,%6,%7}, {%8,%9}, {%0,%1,%2,%3};"
        : "+f"(c[0]), "+f"(c[1]), "+f"(c[2]), "+f"(c[3])
        : "r"(a[0]), "r"(a[1]), "r"(a[2]), "r"(a[3]), "r"(b0), "r"(b1));
}
__device__ __forceinline__ void ldsm4(uint32_t* r, uint32_t addr) {
    asm volatile("ldmatrix.sync.aligned.m8n8.x4.shared.b16 {%0,%1,%2,%3}, [%4];"
                 : "=r"(r[0]), "=r"(r[1]), "=r"(r[2]), "=r"(r[3]) : "r"(addr));
}
__device__ __forceinline__ void ldsm4t(uint32_t* r, uint32_t addr) {
    asm volatile("ldmatrix.sync.aligned.m8n8.x4.trans.shared.b16 {%0,%1,%2,%3}, [%4];"
                 : "=r"(r[0]), "=r"(r[1]), "=r"(r[2]), "=r"(r[3]) : "r"(addr));
}
__device__ __forceinline__ void cp16(uint32_t dst, const void* src) {
    asm volatile("cp.async.cg.shared.global [%0], [%1], 16;"
                 :: "r"(dst), "l"(src));
}
__device__ __forceinline__ void cp_commit() {
    asm volatile("cp.async.commit_group;" ::: "memory");
}
template<int N> __device__ __forceinline__ void cp_wait() {
    asm volatile("cp.async.wait_group %0;" :: "n"(N) : "memory");
}

// Fast exp on FMA pipe: p = 2^(s*log2(e)/8 - 6). MUFU-free.
__device__ __forceinline__ float fexp(float s) {
    float t = fmaf(s, 0.18033688f, -6.0f);
    float z = t + 12582912.0f;
    int   n = __float_as_int(z) - 0x4B400000;
    float f = t - (z - 12582912.0f);
    float p = 0.0013333558f;
    p = fmaf(p, f, 0.0096181291f);
    p = fmaf(p, f, 0.0555041087f);
    p = fmaf(p, f, 0.2402265069f);
    p = fmaf(p, f, 0.6931471806f);
    p = fmaf(p, f, 1.0f);
    return __int_as_float(__float_as_int(p) + (n << 23));
}
__device__ __forceinline__ uint32_t packh2(float a, float b) {
    __half2 h = __halves2half2(__float2half_rn(a), __float2half_rn(b));
    return *(uint32_t*)&h;
}

// ---------------------------------------------------------------------------
// Fused convert prep: all five fp32 arrays -> fp16 in one launch.
// ---------------------------------------------------------------------------
#define CONV_TOTAL (1048576 + 4 * 65536)   // 1310720 float4s

__global__ __launch_bounds__(256) void conv_all_kernel(
    const float* __restrict__ x,  const float* __restrict__ wq,
    const float* __restrict__ wk, const float* __restrict__ wv,
    const float* __restrict__ wo)
{
    int i = blockIdx.x * blockDim.x + threadIdx.x;
    if (i >= CONV_TOTAL) return;
    const float* src; uint2* dst; int off;
    if (i < 1048576)      { src = x;  dst = (uint2*)g_Xh;            off = i; }
    else if (i < 1114112) { src = wq; dst = (uint2*)g_Wh;            off = i - 1048576; }
    else if (i < 1179648) { src = wk; dst = (uint2*)g_Wh + 65536;    off = i - 1114112; }
    else if (i < 1245184) { src = wv; dst = (uint2*)g_Wh + 131072;   off = i - 1179648; }
    else                  { src = wo; dst = (uint2*)g_Woh;           off = i - 1245184; }
    float4 v = ((const float4*)src)[off];
    union { __half h[4]; uint2 u; } H;
    H.h[0] = __float2half_rn(v.x);
    H.h[1] = __float2half_rn(v.y);
    H.h[2] = __float2half_rn(v.z);
    H.h[3] = __float2half_rn(v.w);
    dst[off] = H.u;
}

// ---------------------------------------------------------------------------
// fp16 HGEMM: C[m][n] = sum_k A[m][k]*W[n][k]  (single term, fp32 accum)
// BM=128, BN=64, BK=32, 256 threads, warps 4m x 2n, warp tile 32x32.
// 3-stage cp.async pipeline (wait_group 1), one barrier per K-step.
// Tile rows padded to 80B -> ldmatrix conflict-free without swizzle.
// ---------------------------------------------------------------------------
#define P_XH 0
#define P_WH 10240
#define P_STAGE 15360
#define NKITER (DIM / 32)               // 16
#define PROJ_SMEM (3 * P_STAGE)         // 46080

__device__ __forceinline__ void hgemm_tile(
    const __half* __restrict__ Ah, const __half* __restrict__ Bh,
    int bm, int bn, float c[2][4][4], uint32_t sb32)
{
    const int tid = threadIdx.x;
    const int lane = tid & 31, w = tid >> 5;
    const int wm = w >> 1, wn = w & 1;

    auto issue = [&](int kc, int buf) {
        const int k0 = kc * 32;
        const uint32_t bb = sb32 + buf * P_STAGE;
#pragma unroll
        for (int j = 0; j < 3; j++) {
            int e = tid + j * 256;
            uint32_t dst; const __half* src;
            if (e < 512) {
                int row = e >> 2, ch = e & 3;
                dst = bb + P_XH + row * 80 + ch * 16;
                src = Ah + (size_t)(bm + row) * DIM + k0 + ch * 8;
            } else {
                int i = e - 512;
                int row = i >> 2, ch = i & 3;
                dst = bb + P_WH + row * 80 + ch * 16;
                src = Bh + (size_t)(bn + row) * DIM + k0 + ch * 8;
            }
            cp16(dst, src);
        }
        cp_commit();
    };

    issue(0, 0);
    issue(1, 1);

    const int a_row = (lane & 15);
    const int a_ch = (lane >> 4);
    const int b_row = ((lane >> 4) & 1) * 8 + (lane & 7);
    const int b_ch = ((lane >> 3) & 1);

    int buf = 0;
    for (int kc = 0; kc < NKITER; kc++) {
        if (kc + 1 < NKITER) cp_wait<1>(); else cp_wait<0>();
        __syncthreads();
        if (kc + 2 < NKITER) {
            int nb = buf + 2; if (nb >= 3) nb -= 3;
            issue(kc + 2, nb);
        }
        const uint32_t bb = sb32 + buf * P_STAGE;

#pragma unroll
        for (int kk = 0; kk < 2; kk++) {
            uint32_t ah[2][4], bh[2][4];
#pragma unroll
            for (int mb = 0; mb < 2; mb++) {
                uint32_t off = (wm * 32 + mb * 16 + a_row) * 80
                             + (kk * 2 + a_ch) * 16;
                ldsm4(ah[mb], bb + P_XH + off);
            }
#pragma unroll
            for (int np = 0; np < 2; np++) {
                uint32_t off = (wn * 32 + np * 16 + b_row) * 80
                             + (kk * 2 + b_ch) * 16;
                ldsm4(bh[np], bb + P_WH + off);
            }
#pragma unroll
            for (int mb = 0; mb < 2; mb++)
#pragma unroll
                for (int np = 0; np < 2; np++) {
                    mma16816(c[mb][np * 2],     ah[mb], bh[np][0], bh[np][1]);
                    mma16816(c[mb][np * 2 + 1], ah[mb], bh[np][2], bh[np][3]);
                }
        }
        if (++buf >= 3) buf = 0;
    }
}

// QKV projection: hgemm, epilogue emits fp16
__global__ __launch_bounds__(256, 2) void qkv_hgemm_kernel(
    const float* __restrict__ bq, const float* __restrict__ bk,
    const float* __restrict__ bv)
{
    extern __shared__ char sb[];
    const uint32_t sb32 = smem_u32(sb);
    const int z = blockIdx.z;
    const int bm = blockIdx.y * 128, bn = blockIdx.x * 64;
    const int lane = threadIdx.x & 31, w = threadIdx.x >> 5;
    const int wm = w >> 1, wn = w & 1;

    float c[2][4][4];
#pragma unroll
    for (int mb = 0; mb < 2; mb++)
#pragma unroll
        for (int nb = 0; nb < 4; nb++)
#pragma unroll
            for (int j = 0; j < 4; j++) c[mb][nb][j] = 0.f;

    hgemm_tile(g_Xh, g_Wh + (size_t)z * DIM * DIM, bm, bn, c, sb32);

    const float* bias = (z == 0) ? bq : (z == 1) ? bk : bv;
    __half* outh = (z == 0) ? g_Qh : (z == 1) ? g_Kh : g_Vh;

#pragma unroll
    for (int mb = 0; mb < 2; mb++)
#pragma unroll
        for (int nb = 0; nb < 4; nb++) {
            int r0 = bm + wm * 32 + mb * 16 + (lane >> 2);
            int cc = bn + wn * 32 + nb * 8 + (lane & 3) * 2;
            float b0 = bias[cc], b1 = bias[cc + 1];
            *(uint32_t*)(outh + (size_t)r0 * DIM + cc) =
                packh2(c[mb][nb][0] + b0, c[mb][nb][1] + b1);
            *(uint32_t*)(outh + (size_t)(r0 + 8) * DIM + cc) =
                packh2(c[mb][nb][2] + b0, c[mb][nb][3] + b1);
        }
}

// Output projection: hgemm from g_Oh, fp32 result + bias to d_out
__global__ __launch_bounds__(256, 2) void oproj_hgemm_kernel(
    const float* __restrict__ bo, float* __restrict__ out)
{
    extern __shared__ char sb[];
    const uint32_t sb32 = smem_u32(sb);
    const int bm = blockIdx.y * 128, bn = blockIdx.x * 64;
    const int lane = threadIdx.x & 31, w = threadIdx.x >> 5;
    const int wm = w >> 1, wn = w & 1;

    float c[2][4][4];
#pragma unroll
    for (int mb = 0; mb < 2; mb++)
#pragma unroll
        for (int nb = 0; nb < 4; nb++)
#pragma unroll
            for (int j = 0; j < 4; j++) c[mb][nb][j] = 0.f;

    hgemm_tile(g_Oh, g_Woh, bm, bn, c, sb32);

#pragma unroll
    for (int mb = 0; mb < 2; mb++)
#pragma unroll
        for (int nb = 0; nb < 4; nb++) {
            int r0 = bm + wm * 32 + mb * 16 + (lane >> 2);
            int cc = bn + wn * 32 + nb * 8 + (lane & 3) * 2;
            float b0 = bo[cc], b1 = bo[cc + 1];
            float2 lo = make_float2(c[mb][nb][0] + b0, c[mb][nb][1] + b1);
            float2 hi = make_float2(c[mb][nb][2] + b0, c[mb][nb][3] + b1);
            *(float2*)(out + (size_t)r0 * DIM + cc) = lo;
            *(float2*)(out + (size_t)(r0 + 8) * DIM + cc) = hi;
        }
}

// ---------------------------------------------------------------------------
// mma.sync flash attention, split-KV x4 (2048 CTAs), fp16 partials.
// CTA = 128 q-rows x one (b,h) x one key-range of 1024; 8 warps x m16.
// 3-stage cp.async pipeline (wait_group 1): next tile stays in flight.
// Fixed-shift softmax p = 2^(0.18*s - 6) is split-additive; combine kernel
// does the normalization (NO fences/atomics in this kernel).
// ---------------------------------------------------------------------------
#define TILE_BYTES 8192              // 64 rows * 128 B
#define BUF_BYTES  (2 * TILE_BYTES)  // Kh, Vh
#define ATTN_SMEM  (3 * BUF_BYTES)   // 49152

__global__ __launch_bounds__(256) void flash_attn_mma()
{
    extern __shared__ char sb[];
    const uint32_t sb32 = smem_u32(sb);

    const int tid = threadIdx.x;
    const int lane = tid & 31, w = tid >> 5;
    const int qt = blockIdx.x / NSPLIT, split = blockIdx.x % NSPLIT;
    const int h = blockIdx.y, b = blockIdx.z;
    const int base = b * SEQ, col0 = h * HD;
    const int qrow0 = qt * 128 + w * 16;
    const int kt0 = split * KITER_PER_SPLIT;

    const int r_lo = lane >> 2, kc = (lane & 3) * 2;
    uint32_t qa[4][4];
    {
        const __half* qp = g_Qh + (size_t)(base + qrow0 + r_lo) * DIM + col0 + kc;
#pragma unroll
        for (int kk = 0; kk < 4; kk++) {
            qa[kk][0] = *(const uint32_t*)(qp + kk * 16);
            qa[kk][1] = *(const uint32_t*)(qp + kk * 16 + 8 * DIM);
            qa[kk][2] = *(const uint32_t*)(qp + kk * 16 + 8);
            qa[kk][3] = *(const uint32_t*)(qp + kk * 16 + 8 * DIM + 8);
        }
    }

    float o[8][4];
#pragma unroll
    for (int g = 0; g < 8; g++)
#pragma unroll
        for (int j = 0; j < 4; j++) o[g][j] = 0.f;
    float lsum0 = 0.f, lsum1 = 0.f;

    auto issue_tile = [&](int kt, int buf) {
        const int k0 = kt * 64;
#pragma unroll
        for (int j = 0; j < 4; j++) {
            int e = tid + j * 256;
            int arr = e >> 9;
            int c = e & 511;
            int row = c >> 3, ch = c & 7;
            uint32_t dst = sb32 + buf * BUF_BYTES + arr * TILE_BYTES
                         + row * 128 + ((ch ^ (row & 7)) << 4);
            size_t go = (size_t)(base + k0 + row) * DIM + col0 + ch * 8;
            const __half* src = (arr == 0) ? (g_Kh + go) : (g_Vh + go);
            cp16(dst, src);
        }
        cp_commit();
    };

    issue_tile(kt0, 0);
    issue_tile(kt0 + 1, 1);

    int buf = 0;
    for (int it = 0; it < KITER_PER_SPLIT; it++) {
        if (it + 1 < KITER_PER_SPLIT) cp_wait<1>(); else cp_wait<0>();
        __syncthreads();
        if (it + 2 < KITER_PER_SPLIT) {
            int nb = buf + 2; if (nb >= 3) nb -= 3;
            issue_tile(kt0 + it + 2, nb);
        }

        const uint32_t kb32 = sb32 + buf * BUF_BYTES;

        // ---- S = Q K^T ----
        float s[8][4];
#pragma unroll
        for (int g = 0; g < 8; g++)
#pragma unroll
            for (int j = 0; j < 4; j++) s[g][j] = 0.f;

#pragma unroll
        for (int i = 0; i < 4; i++) {
            int row = i * 16 + ((lane >> 4) & 1) * 8 + (lane & 7);
#pragma unroll
            for (int kk = 0; kk < 4; kk++) {
                int ch = kk * 2 + ((lane >> 3) & 1);
                uint32_t kb[4];
                ldsm4(kb, kb32 + row * 128 + ((ch ^ (row & 7)) << 4));
                mma16816(s[2 * i],     qa[kk], kb[0], kb[1]);
                mma16816(s[2 * i + 1], qa[kk], kb[2], kb[3]);
            }
        }

        // ---- softmax (fixed shift, FMA-pipe exp) + pack P fp16 ----
        uint32_t PH[8][2];
#pragma unroll
        for (int g = 0; g < 8; g++) {
            float p0 = fexp(s[g][0]), p1 = fexp(s[g][1]);
            float p2 = fexp(s[g][2]), p3 = fexp(s[g][3]);
            lsum0 += p0 + p1;
            lsum1 += p2 + p3;
            PH[g][0] = packh2(p0, p1);
            PH[g][1] = packh2(p2, p3);
        }

        // ---- O += P V (single fp16 term) ----
        const uint32_t vh32 = kb32 + TILE_BYTES;
#pragma unroll
        for (int t = 0; t < 4; t++) {
            uint32_t ah[4] = {PH[2 * t][0], PH[2 * t][1],
                              PH[2 * t + 1][0], PH[2 * t + 1][1]};
            int row = t * 16 + ((lane >> 3) & 1) * 8 + (lane & 7);
#pragma unroll
            for (int i = 0; i < 4; i++) {
                int ch = i * 2 + ((lane >> 4) & 1);
                uint32_t vb[4];
                ldsm4t(vb, vh32 + row * 128 + ((ch ^ (row & 7)) << 4));
                mma16816(o[2 * i],     ah, vb[0], vb[1]);
                mma16816(o[2 * i + 1], ah, vb[2], vb[3]);
            }
        }
        if (++buf >= 3) buf = 0;
    }

    // ---- epilogue: unnormalized fp16 partials + l_part ----
    lsum0 += __shfl_xor_sync(0xffffffffu, lsum0, 1);
    lsum0 += __shfl_xor_sync(0xffffffffu, lsum0, 2);
    lsum1 += __shfl_xor_sync(0xffffffffu, lsum1, 1);
    lsum1 += __shfl_xor_sync(0xffffffffu, lsum1, 2);

    if ((lane & 3) == 0) {
        int li = (b * NH + h) * SEQ + qrow0 + r_lo;
        g_lp[split][li] = lsum0;
        g_lp[split][li + 8] = lsum1;
    }

    __half* op = g_Opf[split] + (size_t)(base + qrow0 + r_lo) * DIM + col0 + kc;
#pragma unroll
    for (int g = 0; g < 8; g++) {
        *(uint32_t*)(op + g * 8) = packh2(o[g][0], o[g][1]);
        *(uint32_t*)(op + g * 8 + 8 * DIM) = packh2(o[g][2], o[g][3]);
    }
}

// ---------------------------------------------------------------------------
// Combine: g_Oh[row][col] = fp16( sum_s O_part / sum_s l_part )
// One thread per 16 consecutive cols (two uint4 groups -> MLP 8). fp16 reads.
// ---------------------------------------------------------------------------
__global__ __launch_bounds__(256) void combine_kernel()
{
    int i = blockIdx.x * blockDim.x + threadIdx.x;   // 0 .. MROWS*32-1
    int col = (i & 31) * 16;
    int row = i >> 5;
    int b = row >> 12, s = row & 4095;
    int hh = col >> 6;
    int li = (b * NH + hh) * SEQ + s;
    float l = g_lp[0][li] + g_lp[1][li] + g_lp[2][li] + g_lp[3][li];
    float inv = 1.f / l;
    size_t off = (size_t)row * DIM + col;

    uint4 u[NSPLIT][2];
#pragma unroll
    for (int sp = 0; sp < NSPLIT; sp++) {
        u[sp][0] = *(const uint4*)(g_Opf[sp] + off);
        u[sp][1] = *(const uint4*)(g_Opf[sp] + off + 8);
    }
#pragma unroll
    for (int g = 0; g < 2; g++) {
        float acc[8] = {0, 0, 0, 0, 0, 0, 0, 0};
#pragma unroll
        for (int sp = 0; sp < NSPLIT; sp++) {
            const __half2* hp = (const __half2*)&u[sp][g];
#pragma unroll
            for (int j = 0; j < 4; j++) {
                float2 f = __half22float2(hp[j]);
                acc[j * 2] += f.x;
                acc[j * 2 + 1] += f.y;
            }
        }
        uint4 ou;
        ou.x = packh2(acc[0] * inv, acc[1] * inv);
        ou.y = packh2(acc[2] * inv, acc[3] * inv);
        ou.z = packh2(acc[4] * inv, acc[5] * inv);
        ou.w = packh2(acc[6] * inv, acc[7] * inv);
        *(uint4*)(g_Oh + off + g * 8) = ou;
    }
}

// ---------------------------------------------------------------------------
extern "C" void kernel_launch(void* const* d_in, const int* in_sizes, int n_in,
                              void* d_out, int out_size)
{
    const float* x  = (const float*)d_in[0];
    const float* Wq = (const float*)d_in[1];
    const float* bq = (const float*)d_in[2];
    const float* Wk = (const float*)d_in[3];
    const float* bk = (const float*)d_in[4];
    const float* Wv = (const float*)d_in[5];
    const float* bv = (const float*)d_in[6];
    const float* Wo = (const float*)d_in[7];
    const float* bo = (const float*)d_in[8];
    float* out = (float*)d_out;

    cudaFuncSetAttribute(flash_attn_mma,
                         cudaFuncAttributeMaxDynamicSharedMemorySize, ATTN_SMEM);
    cudaFuncSetAttribute(qkv_hgemm_kernel,
                         cudaFuncAttributeMaxDynamicSharedMemorySize, PROJ_SMEM);
    cudaFuncSetAttribute(oproj_hgemm_kernel,
                         cudaFuncAttributeMaxDynamicSharedMemorySize, PROJ_SMEM);

    conv_all_kernel<<<(CONV_TOTAL + 255) / 256, 256>>>(x, Wq, Wk, Wv, Wo);

    dim3 g1(DIM / 64, MROWS / 128, 3);
    qkv_hgemm_kernel<<<g1, 256, PROJ_SMEM>>>(bq, bk, bv);

    dim3 g2((SEQ / 128) * NSPLIT, NH, BATCH);
    flash_attn_mma<<<g2, 256, ATTN_SMEM>>>();

    combine_kernel<<<MROWS * 32 / 256, 256>>>();

    dim3 g3(DIM / 64, MROWS / 128);
    oproj_hgemm_kernel<<<g3, 256, PROJ_SMEM>>>(bo, out);
}

// round 14
// speedup vs baseline: 1.0159x; 1.0159x over previous
#include <cuda_runtime.h>
#include <cuda_fp16.h>
#include <math.h>
#include <stdint.h>

#define BATCH 2
#define SEQ 4096
#define DIM 512
#define NH 8
#define HD 64
#define MROWS (BATCH * SEQ)   // 8192
#define NSPLIT 4
#define KITER_PER_SPLIT (SEQ / 64 / NSPLIT)   // 16

// Scratch (allocation-free rule: __device__ globals)
__device__ __align__(16) __half g_Xh[MROWS * DIM];
__device__ __align__(16) __half g_Wh[3 * DIM * DIM];
__device__ __align__(16) __half g_Woh[DIM * DIM];
__device__ __align__(16) __half g_Qh[MROWS * DIM];
__device__ __align__(16) __half g_Kh[MROWS * DIM];
__device__ __align__(16) __half g_Vh[MROWS * DIM];
__device__ __align__(16) __half g_Oh[MROWS * DIM];
__device__ __align__(16) __half g_Opf[NSPLIT][MROWS * DIM];       // 32 MB fp16 partials
__device__ __align__(16) float  g_lp[NSPLIT][BATCH * NH * SEQ];   // 1 MB

// ---------------------------------------------------------------------------
// PTX helpers (sm_80-compatible: mma.sync / ldmatrix / cp.async)
// ---------------------------------------------------------------------------
__device__ __forceinline__ uint32_t smem_u32(const void* p) {
    uint32_t a;
    asm("{ .reg .u64 t; cvta.to.shared.u64 t, %1; cvt.u32.u64 %0, t; }"
        : "=r"(a) : "l"(p));
    return a;
}
__device__ __forceinline__ void mma16816(float* c, const uint32_t* a,
                                         uint32_t b0, uint32_t b1) {
    asm volatile(
        "mma.sync.aligned.m16n8k16.row.col.f32.f16.f16.f32 "
        "{%0,%1,%2,%3}, {%4,%5,%6,%7}, {%8,%9}, {%0,%1,%2,%3};"
        : "+f"(c[0]), "+f"(c[1]), "+f"(c[2]), "+f"(c[3])
        : "r"(a[0]), "r"(a[1]), "r"(a[2]), "r"(a[3]), "r"(b0), "r"(b1));
}
__device__ __forceinline__ void ldsm4(uint32_t* r, uint32_t addr) {
    asm volatile("ldmatrix.sync.aligned.m8n8.x4.shared.b16 {%0,%1,%2,%3}, [%4];"
                 : "=r"(r[0]), "=r"(r[1]), "=r"(r[2]), "=r"(r[3]) : "r"(addr));
}
__device__ __forceinline__ void ldsm4t(uint32_t* r, uint32_t addr) {
    asm volatile("ldmatrix.sync.aligned.m8n8.x4.trans.shared.b16 {%0,%1,%2,%3}, [%4];"
                 : "=r"(r[0]), "=r"(r[1]), "=r"(r[2]), "=r"(r[3]) : "r"(addr));
}
__device__ __forceinline__ void cp16(uint32_t dst, const void* src) {
    asm volatile("cp.async.cg.shared.global [%0], [%1], 16;"
                 :: "r"(dst), "l"(src));
}
__device__ __forceinline__ void cp_commit() {
    asm volatile("cp.async.commit_group;" ::: "memory");
}
template<int N> __device__ __forceinline__ void cp_wait() {
    asm volatile("cp.async.wait_group %0;" :: "n"(N) : "memory");
}

// Fast exp on FMA pipe: p = 2^(s*log2(e)/8 - 6). MUFU-free.
__device__ __forceinline__ float fexp(float s) {
    float t = fmaf(s, 0.18033688f, -6.0f);
    float z = t + 12582912.0f;
    int   n = __float_as_int(z) - 0x4B400000;
    float f = t - (z - 12582912.0f);
    float p = 0.0013333558f;
    p = fmaf(p, f, 0.0096181291f);
    p = fmaf(p, f, 0.0555041087f);
    p = fmaf(p, f, 0.2402265069f);
    p = fmaf(p, f, 0.6931471806f);
    p = fmaf(p, f, 1.0f);
    return __int_as_float(__float_as_int(p) + (n << 23));
}
__device__ __forceinline__ uint32_t packh2(float a, float b) {
    __half2 h = __halves2half2(__float2half_rn(a), __float2half_rn(b));
    return *(uint32_t*)&h;
}

// ---------------------------------------------------------------------------
// Fused convert prep: all five fp32 arrays -> fp16 in one launch.
// ---------------------------------------------------------------------------
#define CONV_TOTAL (1048576 + 4 * 65536)   // 1310720 float4s

__global__ __launch_bounds__(256) void conv_all_kernel(
    const float* __restrict__ x,  const float* __restrict__ wq,
    const float* __restrict__ wk, const float* __restrict__ wv,
    const float* __restrict__ wo)
{
    int i = blockIdx.x * blockDim.x + threadIdx.x;
    if (i >= CONV_TOTAL) return;
    const float* src; uint2* dst; int off;
    if (i < 1048576)      { src = x;  dst = (uint2*)g_Xh;            off = i; }
    else if (i < 1114112) { src = wq; dst = (uint2*)g_Wh;            off = i - 1048576; }
    else if (i < 1179648) { src = wk; dst = (uint2*)g_Wh + 65536;    off = i - 1114112; }
    else if (i < 1245184) { src = wv; dst = (uint2*)g_Wh + 131072;   off = i - 1179648; }
    else                  { src = wo; dst = (uint2*)g_Woh;           off = i - 1245184; }
    float4 v = ((const float4*)src)[off];
    union { __half h[4]; uint2 u; } H;
    H.h[0] = __float2half_rn(v.x);
    H.h[1] = __float2half_rn(v.y);
    H.h[2] = __float2half_rn(v.z);
    H.h[3] = __float2half_rn(v.w);
    dst[off] = H.u;
}

// ---------------------------------------------------------------------------
// fp16 HGEMM: C[m][n] = sum_k A[m][k]*W[n][k]  (single term, fp32 accum)
// BM=128, BN=64, BK=32, 256 threads, warps 4m x 2n, warp tile 32x32.
// 3-stage cp.async pipeline (wait_group 1), one barrier per K-step.
// Tile rows padded to 80B -> ldmatrix conflict-free without swizzle.
// ---------------------------------------------------------------------------
#define P_XH 0
#define P_WH 10240
#define P_STAGE 15360
#define NKITER (DIM / 32)               // 16
#define PROJ_SMEM (3 * P_STAGE)         // 46080

__device__ __forceinline__ void hgemm_tile(
    const __half* __restrict__ Ah, const __half* __restrict__ Bh,
    int bm, int bn, float c[2][4][4], uint32_t sb32)
{
    const int tid = threadIdx.x;
    const int lane = tid & 31, w = tid >> 5;
    const int wm = w >> 1, wn = w & 1;

    auto issue = [&](int kc, int buf) {
        const int k0 = kc * 32;
        const uint32_t bb = sb32 + buf * P_STAGE;
#pragma unroll
        for (int j = 0; j < 3; j++) {
            int e = tid + j * 256;
            uint32_t dst; const __half* src;
            if (e < 512) {
                int row = e >> 2, ch = e & 3;
                dst = bb + P_XH + row * 80 + ch * 16;
                src = Ah + (size_t)(bm + row) * DIM + k0 + ch * 8;
            } else {
                int i = e - 512;
                int row = i >> 2, ch = i & 3;
                dst = bb + P_WH + row * 80 + ch * 16;
                src = Bh + (size_t)(bn + row) * DIM + k0 + ch * 8;
            }
            cp16(dst, src);
        }
        cp_commit();
    };

    issue(0, 0);
    issue(1, 1);

    const int a_row = (lane & 15);
    const int a_ch = (lane >> 4);
    const int b_row = ((lane >> 4) & 1) * 8 + (lane & 7);
    const int b_ch = ((lane >> 3) & 1);

    int buf = 0;
    for (int kc = 0; kc < NKITER; kc++) {
        if (kc + 1 < NKITER) cp_wait<1>(); else cp_wait<0>();
        __syncthreads();
        if (kc + 2 < NKITER) {
            int nb = buf + 2; if (nb >= 3) nb -= 3;
            issue(kc + 2, nb);
        }
        const uint32_t bb = sb32 + buf * P_STAGE;

#pragma unroll
        for (int kk = 0; kk < 2; kk++) {
            uint32_t ah[2][4], bh[2][4];
#pragma unroll
            for (int mb = 0; mb < 2; mb++) {
                uint32_t off = (wm * 32 + mb * 16 + a_row) * 80
                             + (kk * 2 + a_ch) * 16;
                ldsm4(ah[mb], bb + P_XH + off);
            }
#pragma unroll
            for (int np = 0; np < 2; np++) {
                uint32_t off = (wn * 32 + np * 16 + b_row) * 80
                             + (kk * 2 + b_ch) * 16;
                ldsm4(bh[np], bb + P_WH + off);
            }
#pragma unroll
            for (int mb = 0; mb < 2; mb++)
#pragma unroll
                for (int np = 0; np < 2; np++) {
                    mma16816(c[mb][np * 2],     ah[mb], bh[np][0], bh[np][1]);
                    mma16816(c[mb][np * 2 + 1], ah[mb], bh[np][2], bh[np][3]);
                }
        }
        if (++buf >= 3) buf = 0;
    }
}

// QKV projection: hgemm, epilogue emits fp16
__global__ __launch_bounds__(256, 2) void qkv_hgemm_kernel(
    const float* __restrict__ bq, const float* __restrict__ bk,
    const float* __restrict__ bv)
{
    extern __shared__ char sb[];
    const uint32_t sb32 = smem_u32(sb);
    const int z = blockIdx.z;
    const int bm = blockIdx.y * 128, bn = blockIdx.x * 64;
    const int lane = threadIdx.x & 31, w = threadIdx.x >> 5;
    const int wm = w >> 1, wn = w & 1;

    float c[2][4][4];
#pragma unroll
    for (int mb = 0; mb < 2; mb++)
#pragma unroll
        for (int nb = 0; nb < 4; nb++)
#pragma unroll
            for (int j = 0; j < 4; j++) c[mb][nb][j] = 0.f;

    hgemm_tile(g_Xh, g_Wh + (size_t)z * DIM * DIM, bm, bn, c, sb32);

    const float* bias = (z == 0) ? bq : (z == 1) ? bk : bv;
    __half* outh = (z == 0) ? g_Qh : (z == 1) ? g_Kh : g_Vh;

#pragma unroll
    for (int mb = 0; mb < 2; mb++)
#pragma unroll
        for (int nb = 0; nb < 4; nb++) {
            int r0 = bm + wm * 32 + mb * 16 + (lane >> 2);
            int cc = bn + wn * 32 + nb * 8 + (lane & 3) * 2;
            float b0 = bias[cc], b1 = bias[cc + 1];
            *(uint32_t*)(outh + (size_t)r0 * DIM + cc) =
                packh2(c[mb][nb][0] + b0, c[mb][nb][1] + b1);
            *(uint32_t*)(outh + (size_t)(r0 + 8) * DIM + cc) =
                packh2(c[mb][nb][2] + b0, c[mb][nb][3] + b1);
        }
}

// Output projection: hgemm from g_Oh, fp32 result + bias to d_out
__global__ __launch_bounds__(256, 2) void oproj_hgemm_kernel(
    const float* __restrict__ bo, float* __restrict__ out)
{
    extern __shared__ char sb[];
    const uint32_t sb32 = smem_u32(sb);
    const int bm = blockIdx.y * 128, bn = blockIdx.x * 64;
    const int lane = threadIdx.x & 31, w = threadIdx.x >> 5;
    const int wm = w >> 1, wn = w & 1;

    float c[2][4][4];
#pragma unroll
    for (int mb = 0; mb < 2; mb++)
#pragma unroll
        for (int nb = 0; nb < 4; nb++)
#pragma unroll
            for (int j = 0; j < 4; j++) c[mb][nb][j] = 0.f;

    hgemm_tile(g_Oh, g_Woh, bm, bn, c, sb32);

#pragma unroll
    for (int mb = 0; mb < 2; mb++)
#pragma unroll
        for (int nb = 0; nb < 4; nb++) {
            int r0 = bm + wm * 32 + mb * 16 + (lane >> 2);
            int cc = bn + wn * 32 + nb * 8 + (lane & 3) * 2;
            float b0 = bo[cc], b1 = bo[cc + 1];
            float2 lo = make_float2(c[mb][nb][0] + b0, c[mb][nb][1] + b1);
            float2 hi = make_float2(c[mb][nb][2] + b0, c[mb][nb][3] + b1);
            *(float2*)(out + (size_t)r0 * DIM + cc) = lo;
            *(float2*)(out + (size_t)(r0 + 8) * DIM + cc) = hi;
        }
}

// ---------------------------------------------------------------------------
// mma.sync flash attention, split-KV x4 (2048 CTAs), fp16 partials.
// CTA = 128 q-rows x one (b,h) x one key-range of 1024; 8 warps x m16.
// Fixed-shift softmax p = 2^(0.18*s - 6) is split-additive; combine kernel
// does the normalization (NO fences/atomics in this kernel).
// ---------------------------------------------------------------------------
#define TILE_BYTES 8192              // 64 rows * 128 B
#define BUF_BYTES  (2 * TILE_BYTES)  // Kh, Vh
#define ATTN_SMEM  (2 * BUF_BYTES)   // 32768

__global__ __launch_bounds__(256) void flash_attn_mma()
{
    extern __shared__ char sb[];
    const uint32_t sb32 = smem_u32(sb);

    const int tid = threadIdx.x;
    const int lane = tid & 31, w = tid >> 5;
    const int qt = blockIdx.x / NSPLIT, split = blockIdx.x % NSPLIT;
    const int h = blockIdx.y, b = blockIdx.z;
    const int base = b * SEQ, col0 = h * HD;
    const int qrow0 = qt * 128 + w * 16;
    const int kt0 = split * KITER_PER_SPLIT;

    const int r_lo = lane >> 2, kc = (lane & 3) * 2;
    uint32_t qa[4][4];
    {
        const __half* qp = g_Qh + (size_t)(base + qrow0 + r_lo) * DIM + col0 + kc;
#pragma unroll
        for (int kk = 0; kk < 4; kk++) {
            qa[kk][0] = *(const uint32_t*)(qp + kk * 16);
            qa[kk][1] = *(const uint32_t*)(qp + kk * 16 + 8 * DIM);
            qa[kk][2] = *(const uint32_t*)(qp + kk * 16 + 8);
            qa[kk][3] = *(const uint32_t*)(qp + kk * 16 + 8 * DIM + 8);
        }
    }

    float o[8][4];
#pragma unroll
    for (int g = 0; g < 8; g++)
#pragma unroll
        for (int j = 0; j < 4; j++) o[g][j] = 0.f;
    float lsum0 = 0.f, lsum1 = 0.f;

    auto issue_tile = [&](int kt, int buf) {
        const int k0 = kt * 64;
#pragma unroll
        for (int j = 0; j < 4; j++) {
            int e = tid + j * 256;
            int arr = e >> 9;
            int c = e & 511;
            int row = c >> 3, ch = c & 7;
            uint32_t dst = sb32 + buf * BUF_BYTES + arr * TILE_BYTES
                         + row * 128 + ((ch ^ (row & 7)) << 4);
            size_t go = (size_t)(base + k0 + row) * DIM + col0 + ch * 8;
            const __half* src = (arr == 0) ? (g_Kh + go) : (g_Vh + go);
            cp16(dst, src);
        }
        cp_commit();
    };

    issue_tile(kt0, 0);

    for (int it = 0; it < KITER_PER_SPLIT; it++) {
        cp_wait<0>();
        __syncthreads();
        if (it + 1 < KITER_PER_SPLIT) issue_tile(kt0 + it + 1, (it + 1) & 1);

        const uint32_t kb32 = sb32 + (it & 1) * BUF_BYTES;

        // ---- S = Q K^T ----
        float s[8][4];
#pragma unroll
        for (int g = 0; g < 8; g++)
#pragma unroll
            for (int j = 0; j < 4; j++) s[g][j] = 0.f;

#pragma unroll
        for (int i = 0; i < 4; i++) {
            int row = i * 16 + ((lane >> 4) & 1) * 8 + (lane & 7);
#pragma unroll
            for (int kk = 0; kk < 4; kk++) {
                int ch = kk * 2 + ((lane >> 3) & 1);
                uint32_t kb[4];
                ldsm4(kb, kb32 + row * 128 + ((ch ^ (row & 7)) << 4));
                mma16816(s[2 * i],     qa[kk], kb[0], kb[1]);
                mma16816(s[2 * i + 1], qa[kk], kb[2], kb[3]);
            }
        }

        // ---- softmax (fixed shift, FMA-pipe exp) + pack P fp16 ----
        uint32_t PH[8][2];
#pragma unroll
        for (int g = 0; g < 8; g++) {
            float p0 = fexp(s[g][0]), p1 = fexp(s[g][1]);
            float p2 = fexp(s[g][2]), p3 = fexp(s[g][3]);
            lsum0 += p0 + p1;
            lsum1 += p2 + p3;
            PH[g][0] = packh2(p0, p1);
            PH[g][1] = packh2(p2, p3);
        }

        // ---- O += P V (single fp16 term) ----
        const uint32_t vh32 = kb32 + TILE_BYTES;
#pragma unroll
        for (int t = 0; t < 4; t++) {
            uint32_t ah[4] = {PH[2 * t][0], PH[2 * t][1],
                              PH[2 * t + 1][0], PH[2 * t + 1][1]};
            int row = t * 16 + ((lane >> 3) & 1) * 8 + (lane & 7);
#pragma unroll
            for (int i = 0; i < 4; i++) {
                int ch = i * 2 + ((lane >> 4) & 1);
                uint32_t vb[4];
                ldsm4t(vb, vh32 + row * 128 + ((ch ^ (row & 7)) << 4));
                mma16816(o[2 * i],     ah, vb[0], vb[1]);
                mma16816(o[2 * i + 1], ah, vb[2], vb[3]);
            }
        }
    }

    // ---- epilogue: unnormalized fp16 partials + l_part ----
    lsum0 += __shfl_xor_sync(0xffffffffu, lsum0, 1);
    lsum0 += __shfl_xor_sync(0xffffffffu, lsum0, 2);
    lsum1 += __shfl_xor_sync(0xffffffffu, lsum1, 1);
    lsum1 += __shfl_xor_sync(0xffffffffu, lsum1, 2);

    if ((lane & 3) == 0) {
        int li = (b * NH + h) * SEQ + qrow0 + r_lo;
        g_lp[split][li] = lsum0;
        g_lp[split][li + 8] = lsum1;
    }

    __half* op = g_Opf[split] + (size_t)(base + qrow0 + r_lo) * DIM + col0 + kc;
#pragma unroll
    for (int g = 0; g < 8; g++) {
        *(uint32_t*)(op + g * 8) = packh2(o[g][0], o[g][1]);
        *(uint32_t*)(op + g * 8 + 8 * DIM) = packh2(o[g][2], o[g][3]);
    }
}

// ---------------------------------------------------------------------------
// Combine: g_Oh[row][col] = fp16( sum_s O_part / sum_s l_part )
// One thread per 8 consecutive cols (always within one head). fp16 reads.
// ---------------------------------------------------------------------------
__global__ __launch_bounds__(256) void combine_kernel()
{
    int i = blockIdx.x * blockDim.x + threadIdx.x;   // 0 .. MROWS*64-1
    int col = (i & 63) * 8;
    int row = i >> 6;
    int b = row >> 12, s = row & 4095;
    int hh = col >> 6;
    int li = (b * NH + hh) * SEQ + s;
    float l = g_lp[0][li] + g_lp[1][li] + g_lp[2][li] + g_lp[3][li];
    float inv = 1.f / l;
    size_t off = (size_t)row * DIM + col;

    float acc[8] = {0, 0, 0, 0, 0, 0, 0, 0};
#pragma unroll
    for (int sp = 0; sp < NSPLIT; sp++) {
        uint4 u = *(const uint4*)(g_Opf[sp] + off);
        const __half2* hp = (const __half2*)&u;
#pragma unroll
        for (int j = 0; j < 4; j++) {
            float2 f = __half22float2(hp[j]);
            acc[j * 2] += f.x;
            acc[j * 2 + 1] += f.y;
        }
    }
    uint4 ou;
    ou.x = packh2(acc[0] * inv, acc[1] * inv);
    ou.y = packh2(acc[2] * inv, acc[3] * inv);
    ou.z = packh2(acc[4] * inv, acc[5] * inv);
    ou.w = packh2(acc[6] * inv, acc[7] * inv);
    *(uint4*)(g_Oh + off) = ou;
}

// ---------------------------------------------------------------------------
extern "C" void kernel_launch(void* const* d_in, const int* in_sizes, int n_in,
                              void* d_out, int out_size)
{
    const float* x  = (const float*)d_in[0];
    const float* Wq = (const float*)d_in[1];
    const float* bq = (const float*)d_in[2];
    const float* Wk = (const float*)d_in[3];
    const float* bk = (const float*)d_in[4];
    const float* Wv = (const float*)d_in[5];
    const float* bv = (const float*)d_in[6];
    const float* Wo = (const float*)d_in[7];
    const float* bo = (const float*)d_in[8];
    float* out = (float*)d_out;

    cudaFuncSetAttribute(flash_attn_mma,
                         cudaFuncAttributeMaxDynamicSharedMemorySize, ATTN_SMEM);
    cudaFuncSetAttribute(qkv_hgemm_kernel,
                         cudaFuncAttributeMaxDynamicSharedMemorySize, PROJ_SMEM);
    cudaFuncSetAttribute(oproj_hgemm_kernel,
                         cudaFuncAttributeMaxDynamicSharedMemorySize, PROJ_SMEM);

    conv_all_kernel<<<(CONV_TOTAL + 255) / 256, 256>>>(x, Wq, Wk, Wv, Wo);

    dim3 g1(DIM / 64, MROWS / 128, 3);
    qkv_hgemm_kernel<<<g1, 256, PROJ_SMEM>>>(bq, bk, bv);

    dim3 g2((SEQ / 128) * NSPLIT, NH, BATCH);
    flash_attn_mma<<<g2, 256, ATTN_SMEM>>>();

    combine_kernel<<<MROWS * 64 / 256, 256>>>();

    dim3 g3(DIM / 64, MROWS / 128);
    oproj_hgemm_kernel<<<g3, 256, PROJ_SMEM>>>(bo, out);
}